// round 15
// baseline (speedup 1.0000x reference)
#include <cuda_runtime.h>
#include <cuda_bf16.h>

// Gather word-offsets (two-choice balanced, 13-bit -> ushort), prescaled G,
// and per-thread B sign bits (16 bits per thread slot).
__device__ __align__(16) unsigned short g_P2h[8192];
__device__ __align__(16) float          g_Gs[8192];
__device__ __align__(16) unsigned short g_Bb[256];

__host__ __device__ __forceinline__ int mapA(int q) {
    return q ^ ((q >> 4) & 28);
}
__host__ __device__ __forceinline__ int mapB(int q) {
    return q ^ ((q >> 4) & 28) ^ ((q >> 7) & 28) ^ ((q >> 4) & 2);
}

// One WARP per gather instruction group (256 groups). Parallel iterative
// two-choice bank balancing (4 rounds; each round every overloaded bank sheds
// its lowest-lane member to its alternate bank). Duplicates broadcast.
// Also prescales G by 1/8192 and packs B sign bits.
__global__ void setup_kernel(const int* __restrict__ P,
                             const float* __restrict__ G,
                             const float* __restrict__ B) {
    const int tid  = blockIdx.x * 256 + threadIdx.x;
    g_Gs[tid] = G[tid] * (1.0f / 8192.0f);   // both 1/sqrt(8192) factors folded

    if (tid < 256) {                          // pack B sign bits for thread slot
        unsigned m = 0;
#pragma unroll
        for (int k = 0; k < 16; k++) {
            int rh = k >> 2, c = k & 3;
            int i = (((rh << 8) | tid) << 2) | c;
            if (B[i] < 0.0f) m |= 1u << k;
        }
        g_Bb[tid] = (unsigned short)m;
    }

    const int g    = tid >> 5;               // group id 0..255
    const int lane = threadIdx.x & 31;
    const int wib  = threadIdx.x >> 5;       // warp in block

    const int W = g >> 5, rh = (g >> 2) & 7, c = g & 3;
    const int e = (W << 10) | (rh << 7) | (lane << 2) | c;
    const int q = P[e] & 4095;
    const int a = mapA(q), b = mapB(q);
    const int bA = a & 31, bB = b & 31;

    // duplicate detection: representative = lowest lane with equal q
    unsigned same = __match_any_sync(0xffffffffu, q);
    const int  rep   = __ffs(same) - 1;
    const bool isrep = (rep == lane);

    __shared__ int counts[8][32];

    int sel = 0;
#pragma unroll
    for (int it = 0; it < 4; it++) {
        counts[wib][lane] = 0;
        __syncwarp();
        const int cur = sel ? bB : bA;
        const int alt = sel ? bA : bB;
        if (isrep) atomicAdd(&counts[wib][cur], 1);
        __syncwarp();
        const int  lc   = counts[wib][cur];
        const int  la   = counts[wib][alt];
        const bool want = isrep && (lc > la + 1);
        const unsigned wm   = __ballot_sync(0xffffffffu, want);
        const unsigned curm = __match_any_sync(0xffffffffu, cur);
        if (want && lane == (__ffs(wm & curm) - 1)) sel ^= 1;
        __syncwarp();
    }
    // duplicates follow their representative (guarantees broadcast)
    sel = __shfl_sync(0xffffffffu, sel, rep);

    g_P2h[e] = (unsigned short)(sel ? (4096 + b) : a);
}

// In-register butterfly stage over register-index bit MASK, N registers.
template <int N, int MASK>
__device__ __forceinline__ void stage(float* v) {
#pragma unroll
    for (int i = 0; i < N; i++) {
        if (!(i & MASK)) {
            float a = v[i], b = v[i ^ MASK];
            v[i] = a + b;
            v[i ^ MASK] = a - b;
        }
    }
}

// x * (+-1) via sign-bit XOR (bit-exact). k is a compile-time constant 0..15.
__device__ __forceinline__ float sgnx(float x, unsigned bits, int k) {
    return __int_as_float(__float_as_int(x) ^
                          (int)((bits << (31 - k)) & 0x80000000u));
}

// One CTA per row, 256 threads (8 warps), 5 CTAs/SM (<=48 regs) for 40
// resident warps. Phase 1: 4096-pt FWHT of x*B (H_8192[y;0]=[H_4096 y;
// H_4096 y]). Phase 2: perm-gather * G, 8192-pt FWHT. All shared patterns
// bank-conflict-free; gather conflicts minimized by two-choice replication
// (copy A words [0,4096), copy B words [4096,8192)).
__global__ __launch_bounds__(256, 5) void fastfood_kernel(
    const float4* __restrict__ x4,   // (rows, 1024) float4
    float4* __restrict__ out4,       // (rows, 2048) float4
    int rows)
{
    __shared__ float sh[8192];                       // 32 KB
    float4* sh4 = reinterpret_cast<float4*>(sh);

    const int row = blockIdx.x;
    if (row >= rows) return;
    const int T = threadIdx.x;
    const int W = T >> 5, L = T & 31;
    const int L10 = L & 3, L42 = L >> 2, L210 = L & 7, L43 = L >> 3;
    const int W10 = W >> 1, W0 = W & 1;

    float v[32];

    // ============ Phase 1: 4096-pt FWHT, i[11:0] ============
    // A1: regs=(rh,c): c=i[1:0], rh=i[11:10]; lanes=i[6:2]; warp=i[9:7]
    {
        const unsigned bits = g_Bb[T];
        const float4* xr = x4 + (size_t)row * 1024;
#pragma unroll
        for (int rh = 0; rh < 4; rh++) {
            int idx = (rh << 8) | (W << 5) | L;      // = i>>2, coalesced
            float4 xv = xr[idx];
            v[rh * 4 + 0] = sgnx(xv.x, bits, rh * 4 + 0);
            v[rh * 4 + 1] = sgnx(xv.y, bits, rh * 4 + 1);
            v[rh * 4 + 2] = sgnx(xv.z, bits, rh * 4 + 2);
            v[rh * 4 + 3] = sgnx(xv.w, bits, rh * 4 + 3);
        }
    }
    stage<16, 1>(v); stage<16, 2>(v); stage<16, 4>(v); stage<16, 8>(v); // i 0,1,10,11

    // W1 (vector, identity map): slot = i>>2.
#pragma unroll
    for (int rh = 0; rh < 4; rh++)
        sh4[(rh << 8) | (W << 5) | L] =
            make_float4(v[rh * 4 + 0], v[rh * 4 + 1], v[rh * 4 + 2], v[rh * 4 + 3]);
    __syncthreads();

    // R1 (scalar): regs=i[8:5], lanes=i[4:0], warp=i[11:9]. word = i.
    {
        int base = (W << 9) | L;
#pragma unroll
        for (int r = 0; r < 16; r++) v[r] = sh[base + (r << 5)];
    }
    stage<16, 1>(v); stage<16, 2>(v); stage<16, 4>(v); stage<16, 8>(v); // i 5,6,7,8
    __syncthreads();

    // W2 (scalar, mapA(i) = i ^ (i[8:6]<<2); i[8:6]=r[3:1])
    {
        int base = (W << 9) | L;
#pragma unroll
        for (int r = 0; r < 16; r++)
            sh[base ^ ((r << 5) | (((r >> 1) & 7) << 2))] = v[r];
    }
    __syncthreads();

    // R2 (scalar, mapA): regs r210=i[4:2], r3=i9; lanes L10=i[1:0], L42=i[8:6];
    //                    warp W0=i5, W21=i[11:10]. word = i ^ (L42<<2).
    int base_r2 = (W10 << 10) | (L42 << 6) | (W0 << 5) | (L42 << 2) | L10;
#pragma unroll
    for (int r = 0; r < 16; r++)
        v[r] = sh[base_r2 ^ ((((r >> 3) & 1) << 9) | ((r & 7) << 2))];
    stage<16, 1>(v); stage<16, 2>(v); stage<16, 4>(v); stage<16, 8>(v); // i 2,3,4,9

    // W3: copy A at mapA(i) (same addresses just read -> no pre-sync),
    //     copy B at 4096+mapB(i) (upper half untouched in phase 1 -> no hazard).
    {
        int baseB = ((4096 | (W10 << 10) | (L42 << 6) | (W0 << 5) | L10))
                    ^ (L42 << 2) ^ (W10 << 3) ^ (W0 << 1);
#pragma unroll
        for (int r = 0; r < 16; r++) {
            sh[base_r2 ^ ((((r >> 3) & 1) << 9) | ((r & 7) << 2))] = v[r];
            sh[baseB  ^ ((((r >> 3) & 1) << 9) | ((((r & 7) ^ (r >> 3)) & 7) << 2))] = v[r];
        }
    }
    __syncthreads();

    // ============ Permutation + G (two-choice ushort offsets) ============
    // A2: e = (W<<10)|(rh<<7)|(L<<2)|c ; regs=(rh,c): c=e[1:0], rh=e[9:7]
    {
        const int2*   P2h2 = reinterpret_cast<const int2*>(g_P2h); // 4 entries
        const float4* G4s  = reinterpret_cast<const float4*>(g_Gs);
#pragma unroll
        for (int rh = 0; rh < 8; rh++) {
            int meta = (W << 8) | (rh << 5) | L;     // = e>>2, coalesced
            int2  pp = P2h2[meta];
            float4 g = G4s[meta];
            unsigned p0 = (unsigned)pp.x & 0xFFFFu, p1 = (unsigned)pp.x >> 16;
            unsigned p2 = (unsigned)pp.y & 0xFFFFu, p3 = (unsigned)pp.y >> 16;
            v[rh * 4 + 0] = sh[p0] * g.x;
            v[rh * 4 + 1] = sh[p1] * g.y;
            v[rh * 4 + 2] = sh[p2] * g.z;
            v[rh * 4 + 3] = sh[p3] * g.w;
        }
    }
    __syncthreads();   // all gathers done before W4 overwrites

    // ============ Phase 2: 8192-pt FWHT, e[12:0] ============
    stage<32, 1>(v); stage<32, 2>(v); stage<32, 4>(v);
    stage<32, 8>(v); stage<32, 16>(v);               // e 0,1,7,8,9

    // Storage map for trips 4/5:
    // w(e) = (e[12:10]<<10)|(e[6:5]<<8)|(e[9:7]<<5)|((e[4:2]^e[9:7])<<2)|e[1:0]
    // W4 (vector): slot = (W<<8)|(L43<<6)|(rh<<3)|(L210^rh).
    {
        int baseW4 = (W << 8) | (L43 << 6) | L210;
#pragma unroll
        for (int rh = 0; rh < 8; rh++)
            sh4[baseW4 ^ (rh * 9)] =
                make_float4(v[rh * 4 + 0], v[rh * 4 + 1], v[rh * 4 + 2], v[rh * 4 + 3]);
    }
    __syncthreads();

    // R4 (scalar): regs r=e[6:2]; lanes L10=e[1:0], L42=e[9:7]; warp=e[12:10].
    int baseR4 = (W << 10) | (L42 << 5) | (L42 << 2) | L10;
#pragma unroll
    for (int r = 0; r < 32; r++)
        v[r] = sh[baseR4 ^ (((r >> 3) << 8) | ((r & 7) << 2))];
    stage<32, 1>(v); stage<32, 2>(v); stage<32, 4>(v);
    stage<32, 8>(v); stage<32, 16>(v);               // e 2,3,4,5,6
    // W5: same addresses (no pre-sync).
#pragma unroll
    for (int r = 0; r < 32; r++)
        sh[baseR4 ^ (((r >> 3) << 8) | ((r & 7) << 2))] = v[r];
    __syncthreads();

    // R5 (vector): regs=(rp,c): c=e[1:0], rp=e[12:10]; lanes=e[6:2]; warp=e[9:7].
    {
        int baseR5 = (L43 << 6) | (W << 3) | (L210 ^ W);
#pragma unroll
        for (int rp = 0; rp < 8; rp++) {
            float4 t = sh4[baseR5 + (rp << 8)];
            v[rp * 4 + 0] = t.x; v[rp * 4 + 1] = t.y;
            v[rp * 4 + 2] = t.z; v[rp * 4 + 3] = t.w;
        }
    }
    stage<32, 4>(v); stage<32, 8>(v); stage<32, 16>(v); // e 10,11,12

    // ============ Coalesced store (scale folded into G) ============
#pragma unroll
    for (int rp = 0; rp < 8; rp++)
        out4[(size_t)row * 2048 + (rp << 8) + (W << 5) + L] =
            make_float4(v[rp * 4 + 0], v[rp * 4 + 1],
                        v[rp * 4 + 2], v[rp * 4 + 3]);
}

extern "C" void kernel_launch(void* const* d_in, const int* in_sizes, int n_in,
                              void* d_out, int out_size) {
    const float* x = (const float*)d_in[0];
    const float* B = (const float*)d_in[1];
    const float* G = (const float*)d_in[2];
    const int*   P = (const int*)d_in[3];
    float* out = (float*)d_out;

    int rows = in_sizes[0] / 4096;

    setup_kernel<<<32, 256>>>(P, G, B);
    fastfood_kernel<<<rows, 256>>>(
        (const float4*)x, (float4*)out, rows);
}

// round 17
// speedup vs baseline: 1.2656x; 1.2656x over previous
#include <cuda_runtime.h>
#include <cuda_bf16.h>

// Gather word-offsets (two-choice balanced, 13-bit -> ushort), prescaled G
// (both permuted to the phase-2 "A2'" element order), and B sign bits.
__device__ __align__(16) unsigned short g_P2h[8192];
__device__ __align__(16) float          g_Gs[8192];
__device__ __align__(16) unsigned short g_Bb[256];

typedef unsigned long long ull;

__host__ __device__ __forceinline__ int mapA(int q) {
    return q ^ ((q >> 4) & 28);
}
__host__ __device__ __forceinline__ int mapB(int q) {
    return q ^ ((q >> 4) & 28) ^ ((q >> 7) & 28) ^ ((q >> 4) & 2);
}

// Element order for phase 2 tables (A2' layout, e0/e2 thread-local):
// e12..e10=W, e9..e7=rh, e6..e3=L[4:1], e2=c1, e1=L0, e0=c0.
__host__ __device__ __forceinline__ int eperm(int W, int rh, int lane, int c) {
    return (W << 10) | (rh << 7) | ((lane >> 1) << 3) |
           (((c >> 1) & 1) << 2) | ((lane & 1) << 1) | (c & 1);
}

// One WARP per gather instruction group (256 groups). Parallel iterative
// two-choice bank balancing (4 rounds). Duplicates broadcast. Prescales G.
__global__ void setup_kernel(const int* __restrict__ P,
                             const float* __restrict__ G,
                             const float* __restrict__ B) {
    const int tid = blockIdx.x * 256 + threadIdx.x;
    {   // G permuted to table order, scaled by 1/8192 (both 1/sqrt factors)
        int Wt = tid >> 10, rht = (tid >> 7) & 7, Lt = (tid >> 2) & 31, ct = tid & 3;
        g_Gs[tid] = G[eperm(Wt, rht, Lt, ct)] * (1.0f / 8192.0f);
    }

    if (tid < 256) {                          // pack B sign bits (phase 1)
        unsigned m = 0;
#pragma unroll
        for (int k = 0; k < 16; k++) {
            int rh = k >> 2, c = k & 3;
            int i = (((rh << 8) | tid) << 2) | c;
            if (B[i] < 0.0f) m |= 1u << k;
        }
        g_Bb[tid] = (unsigned short)m;
    }

    const int g    = tid >> 5;               // group id 0..255
    const int lane = threadIdx.x & 31;
    const int wib  = threadIdx.x >> 5;

    const int W = g >> 5, rh = (g >> 2) & 7, c = g & 3;
    const int et = (W << 10) | (rh << 7) | (lane << 2) | c;   // table index
    const int q  = P[eperm(W, rh, lane, c)] & 4095;           // element value
    const int a = mapA(q), b = mapB(q);
    const int bA = a & 31, bB = b & 31;

    unsigned same = __match_any_sync(0xffffffffu, q);
    const int  rep   = __ffs(same) - 1;
    const bool isrep = (rep == lane);

    __shared__ int counts[8][32];

    int sel = 0;
#pragma unroll
    for (int it = 0; it < 4; it++) {
        counts[wib][lane] = 0;
        __syncwarp();
        const int cur = sel ? bB : bA;
        const int alt = sel ? bA : bB;
        if (isrep) atomicAdd(&counts[wib][cur], 1);
        __syncwarp();
        const int  lc   = counts[wib][cur];
        const int  la   = counts[wib][alt];
        const bool want = isrep && (lc > la + 1);
        const unsigned wm   = __ballot_sync(0xffffffffu, want);
        const unsigned curm = __match_any_sync(0xffffffffu, cur);
        if (want && lane == (__ffs(wm & curm) - 1)) sel ^= 1;
        __syncwarp();
    }
    sel = __shfl_sync(0xffffffffu, sel, rep);

    g_P2h[et] = (unsigned short)(sel ? (4096 + b) : a);
}

// ---------- scalar helpers (phase 1) ----------
template <int N, int MASK>
__device__ __forceinline__ void stage(float* v) {
#pragma unroll
    for (int i = 0; i < N; i++) {
        if (!(i & MASK)) {
            float a = v[i], b = v[i ^ MASK];
            v[i] = a + b;
            v[i ^ MASK] = a - b;
        }
    }
}
__device__ __forceinline__ float sgnx(float x, unsigned bits, int k) {
    return __int_as_float(__float_as_int(x) ^
                          (int)((bits << (31 - k)) & 0x80000000u));
}

// ---------- packed f32x2 helpers (phase 2) ----------
#define NEG1X2 0xBF800000BF800000ULL

__device__ __forceinline__ ull pk(float x, float y) {
    float2 f = make_float2(x, y);
    return *reinterpret_cast<ull*>(&f);
}
// (x,y) -> (x+y, x-y) within the pair (scalar; zero-asm, correctness-safe)
__device__ __forceinline__ ull bfly0(ull v) {
    float2 f = *reinterpret_cast<float2*>(&v);
    float2 r = make_float2(f.x + f.y, f.x - f.y);
    return *reinterpret_cast<ull*>(&r);
}
// packed butterfly stage over pair-index bit M (16 pairs)
template <int M>
__device__ __forceinline__ void pstage(ull* p) {
#pragma unroll
    for (int i = 0; i < 16; i++) {
        if (!(i & M)) {
            ull u = p[i], w = p[i ^ M];
            asm("add.rn.f32x2 %0, %1, %2;" : "=l"(p[i]) : "l"(u), "l"(w));
            asm("fma.rn.f32x2 %0, %1, %2, %3;"
                : "=l"(p[i ^ M]) : "l"(w), "l"((ull)NEG1X2), "l"(u));
        }
    }
}

// One CTA per row, 256 threads (8 warps), 4 CTAs/SM. Phase 1: 4096-pt FWHT of
// x*B (scalar path, r12-proven). Phase 2: perm-gather * G, 8192-pt FWHT in
// PACKED f32x2 (e0 = pack lane). Shared trips use dword indices with the
// storage map Ma(h)=h^(h4<<1)^(h6<<2)^(h7<<3), composed by XOR on the INDEX
// (C++ array indexing owns the base). All patterns bank-conflict-free.
__global__ __launch_bounds__(256, 4) void fastfood_kernel(
    const float4* __restrict__ x4,   // (rows, 1024) float4
    float4* __restrict__ out4,       // (rows, 2048) float4
    int rows)
{
    __shared__ __align__(16) float sh[8192];         // 32 KB
    float4* sh4 = reinterpret_cast<float4*>(sh);
    ull*    sh8 = reinterpret_cast<ull*>(sh);

    const int row = blockIdx.x;
    if (row >= rows) return;
    const int T = threadIdx.x;
    const int W = T >> 5, L = T & 31;
    const int L10 = L & 3, L42 = L >> 2;
    const int W10 = W >> 1, W0 = W & 1;

    float v[16];

    // ============ Phase 1: 4096-pt FWHT, i[11:0] (unchanged from r12) ========
    {
        const unsigned bits = g_Bb[T];
        const float4* xr = x4 + (size_t)row * 1024;
#pragma unroll
        for (int rh = 0; rh < 4; rh++) {
            int idx = (rh << 8) | (W << 5) | L;
            float4 xv = xr[idx];
            v[rh * 4 + 0] = sgnx(xv.x, bits, rh * 4 + 0);
            v[rh * 4 + 1] = sgnx(xv.y, bits, rh * 4 + 1);
            v[rh * 4 + 2] = sgnx(xv.z, bits, rh * 4 + 2);
            v[rh * 4 + 3] = sgnx(xv.w, bits, rh * 4 + 3);
        }
    }
    stage<16, 1>(v); stage<16, 2>(v); stage<16, 4>(v); stage<16, 8>(v); // i 0,1,10,11

#pragma unroll
    for (int rh = 0; rh < 4; rh++)
        sh4[(rh << 8) | (W << 5) | L] =
            make_float4(v[rh * 4 + 0], v[rh * 4 + 1], v[rh * 4 + 2], v[rh * 4 + 3]);
    __syncthreads();

    {
        int base = (W << 9) | L;
#pragma unroll
        for (int r = 0; r < 16; r++) v[r] = sh[base + (r << 5)];
    }
    stage<16, 1>(v); stage<16, 2>(v); stage<16, 4>(v); stage<16, 8>(v); // i 5,6,7,8
    __syncthreads();

    {
        int base = (W << 9) | L;
#pragma unroll
        for (int r = 0; r < 16; r++)
            sh[base ^ ((r << 5) | (((r >> 1) & 7) << 2))] = v[r];
    }
    __syncthreads();

    int base_r2 = (W10 << 10) | (L42 << 6) | (W0 << 5) | (L42 << 2) | L10;
#pragma unroll
    for (int r = 0; r < 16; r++)
        v[r] = sh[base_r2 ^ ((((r >> 3) & 1) << 9) | ((r & 7) << 2))];
    stage<16, 1>(v); stage<16, 2>(v); stage<16, 4>(v); stage<16, 8>(v); // i 2,3,4,9

    {
        int baseB = ((4096 | (W10 << 10) | (L42 << 6) | (W0 << 5) | L10))
                    ^ (L42 << 2) ^ (W10 << 3) ^ (W0 << 1);
#pragma unroll
        for (int r = 0; r < 16; r++) {
            sh[base_r2 ^ ((((r >> 3) & 1) << 9) | ((r & 7) << 2))] = v[r];
            sh[baseB  ^ ((((r >> 3) & 1) << 9) | ((((r & 7) ^ (r >> 3)) & 7) << 2))] = v[r];
        }
    }
    __syncthreads();

    // ============ Permutation + G -> packed pairs (A2' layout) ============
    // pv[j], j bits: j0=e2, j1=e7, j2=e8, j3=e9; pack lane = e0.
    ull pv[16];
    {
        const int2*   P2h2 = reinterpret_cast<const int2*>(g_P2h);
        const float4* G4s  = reinterpret_cast<const float4*>(g_Gs);
#pragma unroll
        for (int rh = 0; rh < 8; rh++) {
            int meta = (W << 8) | (rh << 5) | L;
            int2  pp = P2h2[meta];
            float4 g = G4s[meta];
            unsigned p0 = (unsigned)pp.x & 0xFFFFu, p1 = (unsigned)pp.x >> 16;
            unsigned p2 = (unsigned)pp.y & 0xFFFFu, p3 = (unsigned)pp.y >> 16;
            pv[rh * 2 + 0] = pk(sh[p0] * g.x, sh[p1] * g.y);
            pv[rh * 2 + 1] = pk(sh[p2] * g.z, sh[p3] * g.w);
        }
    }
    __syncthreads();   // all gathers done before W4 overwrites

    // ============ Phase 2 seg1: stages {e0, e2, e7, e8, e9} ============
#pragma unroll
    for (int j = 0; j < 16; j++) pv[j] = bfly0(pv[j]);
    pstage<1>(pv); pstage<2>(pv); pstage<4>(pv); pstage<8>(pv);

    // W4 (STS.64): dword h: h0=e1=L0, h2..h5=e3..e6=L[4:1], h9..11=W;
    // j -> h1,h6,h7,h8. Ma: b1^=h4(L3), b2^=h6(j1), b3^=h7(j2).
    {
        unsigned bh = (unsigned)(((L & 1) | (((L >> 1) & 15) << 2) | (W << 9))
                                 ^ (((L >> 3) & 1) << 1));
#pragma unroll
        for (int j = 0; j < 16; j++) {
            unsigned off = ((j & 1) << 1) | (((j >> 1) & 1) << 6) |
                           (((j >> 2) & 1) << 7) | (((j >> 3) & 1) << 8) |
                           (((j >> 1) & 1) << 2) | (((j >> 2) & 1) << 3);
            sh8[bh ^ off] = pv[j];
        }
    }
    __syncthreads();

    // R4' (LDS.64): pairs q=e3..e6 -> h2..h5; lanes h0=L0,h1=L1,h6..8=L[4:2];
    // warp h9..11=W. Ma: b1^=h4(q2), b2^=h6(L2), b3^=h7(L3).
    const unsigned bhR = (unsigned)(((L & 3) | (((L >> 2) & 7) << 6) | (W << 9))
                                    ^ (((L >> 2) & 1) << 2) ^ (((L >> 3) & 1) << 3));
#pragma unroll
    for (int q = 0; q < 16; q++) {
        unsigned off = ((q & 1) << 2) | (((q >> 1) & 1) << 3) |
                       (((q >> 2) & 1) << 4) | (((q >> 3) & 1) << 5) |
                       (((q >> 2) & 1) << 1);
        pv[q] = sh8[bhR ^ off];
    }

    // seg2: stages {e3, e4, e5, e6}
    pstage<1>(pv); pstage<2>(pv); pstage<4>(pv); pstage<8>(pv);

    // W5': same addresses (no pre-sync)
#pragma unroll
    for (int q = 0; q < 16; q++) {
        unsigned off = ((q & 1) << 2) | (((q >> 1) & 1) << 3) |
                       (((q >> 2) & 1) << 4) | (((q >> 3) & 1) << 5) |
                       (((q >> 2) & 1) << 1);
        sh8[bhR ^ off] = pv[q];
    }
    __syncthreads();

    // R5'' (LDS.128): pairs t0=e1(in-access), k=e[12:10] -> h9..11;
    // lanes h1..h5 = L (e2..e6); warp h6..8 = W (e7..e9).
    // Ma: b1^=h4(L3), b2^=h6(W0), b3^=h7(W1).
    {
        const ulonglong2* sh16 = reinterpret_cast<const ulonglong2*>(sh);
        unsigned bh5 = (unsigned)(((L << 1) | (W << 6))
                                  ^ (((L >> 3) & 1) << 1) ^ ((W & 1) << 2)
                                  ^ (((W >> 1) & 1) << 3));
        unsigned b2i = bh5 >> 1;                  // ulonglong2 index (bit0 of bh5 = 0)
#pragma unroll
        for (int k = 0; k < 8; k++) {
            ulonglong2 t = sh16[b2i ^ (unsigned)(k << 8)];
            pv[2 * k]     = t.x;
            pv[2 * k + 1] = t.y;
        }
    }

    // seg3: stages {e1, e10, e11, e12}
    pstage<1>(pv); pstage<2>(pv); pstage<4>(pv); pstage<8>(pv);

    // ============ Coalesced store: 8 x 16B (scale folded into G) ============
    {
        ulonglong2* op = reinterpret_cast<ulonglong2*>(
            out4 + (size_t)row * 2048 + (W << 5) + L);
#pragma unroll
        for (int k = 0; k < 8; k++) {
            ulonglong2 t;
            t.x = pv[2 * k];
            t.y = pv[2 * k + 1];
            op[k << 8] = t;
        }
    }
}

extern "C" void kernel_launch(void* const* d_in, const int* in_sizes, int n_in,
                              void* d_out, int out_size) {
    const float* x = (const float*)d_in[0];
    const float* B = (const float*)d_in[1];
    const float* G = (const float*)d_in[2];
    const int*   P = (const int*)d_in[3];
    float* out = (float*)d_out;

    int rows = in_sizes[0] / 4096;

    setup_kernel<<<32, 256>>>(P, G, B);
    fastfood_kernel<<<rows, 256>>>(
        (const float4*)x, (float4*)out, rows);
}